// round 15
// baseline (speedup 1.0000x reference)
#include <cuda_runtime.h>
#include <math.h>

#define BB 2
#define TT 2048
#define DD 1024
#define HH 16
#define HIDD 4096
#define BT (BB*TT)   // 4096 rows

// ---------------- scratch ----------------
__device__ float g_xn [BB*TT*DD];
__device__ float g_y  [BB*TT*DD];
__device__ float g_q  [BB*TT*DD];
__device__ float g_k  [BB*TT*DD];
__device__ float g_v  [BB*TT*DD];
__device__ float g_ao [BB*TT*DD];
__device__ float g_x1 [BB*TT*DD];
__device__ float g_xn2[BB*TT*DD];
__device__ float g_hb [BB*TT*HIDD];
__device__ float g_w  [12*1024*1024];   // rounded TRANSPOSED weights [n][k]
__device__ float g_e1 [BB*64*16*DD];    // ema chunk h_end   [b][g][n][d]
__device__ float g_e2 [BB*64*16*DD];    // ema chunk h_start [b][g][n][d]
__device__ float2 g_cs[TT*16];          // rope cos/sin table [t][i]

// ---------------- helpers ----------------
__device__ __forceinline__ unsigned f2tf32(float x)
{
    unsigned r;
    asm("cvt.rna.tf32.f32 %0, %1;" : "=r"(r) : "f"(x));
    return r;
}
__device__ __forceinline__ float f2tf32f(float x) { return __uint_as_float(f2tf32(x)); }
__device__ __forceinline__ float4 cvt4(float4 v)
{
    return make_float4(f2tf32f(v.x), f2tf32f(v.y), f2tf32f(v.z), f2tf32f(v.w));
}

__device__ __forceinline__ void ldmx4(unsigned& a0, unsigned& a1, unsigned& a2, unsigned& a3,
                                      unsigned addr)
{
    asm volatile("ldmatrix.sync.aligned.m8n8.x4.shared.b16 {%0,%1,%2,%3}, [%4];"
                 : "=r"(a0), "=r"(a1), "=r"(a2), "=r"(a3) : "r"(addr));
}
__device__ __forceinline__ void mma_tf32(float* d, const unsigned* a, unsigned b0, unsigned b1)
{
    asm volatile(
        "mma.sync.aligned.m16n8k8.row.col.f32.tf32.tf32.f32 "
        "{%0,%1,%2,%3}, {%4,%5,%6,%7}, {%8,%9}, {%0,%1,%2,%3};\n"
        : "+f"(d[0]), "+f"(d[1]), "+f"(d[2]), "+f"(d[3])
        : "r"(a[0]), "r"(a[1]), "r"(a[2]), "r"(a[3]), "r"(b0), "r"(b1));
}
__device__ __forceinline__ void cpasync16(void* smem, const void* gmem)
{
    unsigned s = (unsigned)__cvta_generic_to_shared(smem);
    asm volatile("cp.async.cg.shared.global [%0], [%1], 16;" :: "r"(s), "l"(gmem));
}
#define CP_COMMIT() asm volatile("cp.async.commit_group;")
#define CP_WAIT(n)  asm volatile("cp.async.wait_group %0;" :: "n"(n))

// ---------------- rope cos/sin table ----------------
__global__ void cstab_kernel(float2* __restrict__ cs)
{
    int idx = blockIdx.x * blockDim.x + threadIdx.x;   // TT*16
    int i = idx & 15;
    int t = idx >> 4;
    double fd = pow(10000.0, -(double)i / 16.0);
    float freq = (float)fd;
    float ang = (float)t * freq;
    double da = (double)ang;
    cs[idx] = make_float2((float)cos(da), (float)sin(da));
}

// ---------------- weight transpose + tf32 round ----------------
__global__ void wtrans_kernel(const float* __restrict__ wq, const float* __restrict__ wk,
                              const float* __restrict__ wv, const float* __restrict__ wo,
                              const float* __restrict__ win, const float* __restrict__ wout,
                              float* __restrict__ dst)
{
    __shared__ float tile[32][33];
    int t = blockIdx.x;
    const float* src; int K, N; size_t doff;
    if (t < 4096) {
        int m = t >> 10; t &= 1023;
        src = (m == 0) ? wq : (m == 1) ? wk : (m == 2) ? wv : wo;
        K = 1024; N = 1024; doff = (size_t)m * 1024 * 1024;
    } else if (t < 8192) {
        t -= 4096; src = win;  K = 1024; N = 4096; doff = (size_t)4 * 1024 * 1024;
    } else {
        t -= 8192; src = wout; K = 4096; N = 1024; doff = (size_t)8 * 1024 * 1024;
    }
    int ktiles = K >> 5;
    int k0 = (t % ktiles) << 5;
    int n0 = (t / ktiles) << 5;
    int tx = threadIdx.x, ty = threadIdx.y;   // (32, 8)
    #pragma unroll
    for (int j = 0; j < 4; j++)
        tile[ty + j * 8][tx] = src[(size_t)(k0 + ty + j * 8) * N + n0 + tx];
    __syncthreads();
    #pragma unroll
    for (int j = 0; j < 4; j++)
        dst[doff + (size_t)(n0 + ty + j * 8) * K + k0 + tx] = f2tf32f(tile[tx][ty + j * 8]);
}

// ---------------- rmsnorm ----------------
__global__ void rmsnorm_kernel(const float* __restrict__ x, const float* __restrict__ g,
                               float* __restrict__ out, int rnd)
{
    int row = blockIdx.x;
    int tid = threadIdx.x;
    const float4* xr = (const float4*)(x + (size_t)row * DD);
    float4 v = xr[tid];
    float s = v.x*v.x + v.y*v.y + v.z*v.z + v.w*v.w;
    #pragma unroll
    for (int o = 16; o; o >>= 1) s += __shfl_xor_sync(0xffffffffu, s, o);
    __shared__ float red[8];
    if ((tid & 31) == 0) red[tid >> 5] = s;
    __syncthreads();
    float tot = red[0]+red[1]+red[2]+red[3]+red[4]+red[5]+red[6]+red[7];
    float inv = rsqrtf(tot * (1.0f / (float)DD) + 1e-6f);
    const float4* gr = (const float4*)g;
    float4 gv = gr[tid];
    float4 o4;
    o4.x = gv.x * (v.x * inv);
    o4.y = gv.y * (v.y * inv);
    o4.z = gv.z * (v.z * inv);
    o4.w = gv.w * (v.w * inv);
    if (rnd) o4 = cvt4(o4);
    ((float4*)(out + (size_t)row * DD))[tid] = o4;
}

// ---------------- EMA chunked scan (G=64 chunks of 32 steps) ----------------
#define EG 64
#define ECH 32

__global__ void ema1_kernel(const float* __restrict__ xn,
                            const float* __restrict__ ap, const float* __restrict__ dp,
                            const float* __restrict__ beta,
                            float* __restrict__ hend)
{
    int idx = blockIdx.x * blockDim.x + threadIdx.x;   // 2^17
    int d = idx & 1023;
    int g = (idx >> 10) & (EG - 1);
    int b = idx >> 16;
    float dec[16], ab[16], h[16];
    #pragma unroll
    for (int n = 0; n < 16; n++) {
        int dn = d * 16 + n;
        float a   = 1.0f / (1.0f + expf(-ap[dn]));
        float ddv = 1.0f / (1.0f + expf(-dp[dn]));
        dec[n] = 1.0f - a * ddv;
        ab[n]  = a * beta[dn];
        h[n]   = 0.0f;
    }
    const float* xp = xn + ((size_t)b * TT + g * ECH) * DD + d;
    #pragma unroll 4
    for (int t = 0; t < ECH; t++) {
        float u = xp[(size_t)t * DD];
        #pragma unroll
        for (int n = 0; n < 16; n++)
            h[n] = fmaf(dec[n], h[n], ab[n] * u);
    }
    size_t base = ((size_t)b * EG + g) * 16 * DD + d;
    #pragma unroll
    for (int n = 0; n < 16; n++)
        hend[base + (size_t)n * DD] = h[n];
}

__global__ void ema2_kernel(const float* __restrict__ hend,
                            const float* __restrict__ ap, const float* __restrict__ dp,
                            float* __restrict__ hstart)
{
    int idx = blockIdx.x * blockDim.x + threadIdx.x;   // 2^15
    int d = idx & 1023;
    int n = (idx >> 10) & 15;
    int b = idx >> 14;
    int dn = d * 16 + n;
    float a   = 1.0f / (1.0f + expf(-ap[dn]));
    float ddv = 1.0f / (1.0f + expf(-dp[dn]));
    float dec = 1.0f - a * ddv;
    float dch = dec;
    #pragma unroll
    for (int j = 0; j < 5; j++) dch *= dch;            // dec^32
    size_t base = ((size_t)b * EG * 16 + n) * DD + d;
    float H = 0.0f;
    #pragma unroll
    for (int gg = 0; gg < EG; gg += 16) {
        float hv[16];
        #pragma unroll
        for (int j = 0; j < 16; j++)
            hv[j] = hend[base + (size_t)(gg + j) * 16 * DD];
        #pragma unroll
        for (int j = 0; j < 16; j++) {
            hstart[base + (size_t)(gg + j) * 16 * DD] = H;
            H = fmaf(dch, H, hv[j]);
        }
    }
}

__global__ void ema3_kernel(const float* __restrict__ xn,
                            const float* __restrict__ ap, const float* __restrict__ dp,
                            const float* __restrict__ beta, const float* __restrict__ eta,
                            const float* __restrict__ hstart,
                            float* __restrict__ y)
{
    int idx = blockIdx.x * blockDim.x + threadIdx.x;   // 2^17
    int d = idx & 1023;
    int g = (idx >> 10) & (EG - 1);
    int b = idx >> 16;
    float dec[16], ab[16], et[16], h[16];
    #pragma unroll
    for (int n = 0; n < 16; n++) {
        int dn = d * 16 + n;
        float a   = 1.0f / (1.0f + expf(-ap[dn]));
        float ddv = 1.0f / (1.0f + expf(-dp[dn]));
        dec[n] = 1.0f - a * ddv;
        ab[n]  = a * beta[dn];
        et[n]  = eta[dn];
        h[n]   = hstart[(((size_t)b * EG + g) * 16 + n) * DD + d];
    }
    const float* xp = xn + ((size_t)b * TT + g * ECH) * DD + d;
    float*       yp = y  + ((size_t)b * TT + g * ECH) * DD + d;
    #pragma unroll 4
    for (int t = 0; t < ECH; t++) {
        float u = xp[(size_t)t * DD];
        float s0 = 0.f, s1 = 0.f, s2 = 0.f, s3 = 0.f;
        #pragma unroll
        for (int n = 0; n < 16; n += 4) {
            h[n]   = fmaf(dec[n],   h[n],   ab[n]   * u);
            h[n+1] = fmaf(dec[n+1], h[n+1], ab[n+1] * u);
            h[n+2] = fmaf(dec[n+2], h[n+2], ab[n+2] * u);
            h[n+3] = fmaf(dec[n+3], h[n+3], ab[n+3] * u);
            s0 = fmaf(et[n],   h[n],   s0);
            s1 = fmaf(et[n+1], h[n+1], s1);
            s2 = fmaf(et[n+2], h[n+2], s2);
            s3 = fmaf(et[n+3], h[n+3], s3);
        }
        yp[(size_t)t * DD] = f2tf32f((s0 + s1) + (s2 + s3));
    }
}

// ---------------- tf32 GEMM core: 128x128xK32, cp.async 3-stage, all-ldmatrix ---
__device__ __forceinline__ float gelu_tanh(float x)
{
    float z = 0.7978845608028654f * (x + 0.044715f * x * x * x);
    float e = __expf(2.0f * z);
    float t = 1.0f - 2.0f / (e + 1.0f);
    return 0.5f * x * (1.0f + t);
}

#define GSTAGES 3
#define TS_STRIDE (128*36)
#define SMEM_GEMM ((GSTAGES * 2 * TS_STRIDE) * 4)

template<int EPI, bool RND, bool ROPE>
__device__ __forceinline__ void gemm_core(const float* __restrict__ A,
                                          const float* __restrict__ Bt,
                                          float* __restrict__ C,
                                          const float* __restrict__ bias,
                                          const float* __restrict__ resid,
                                          const float2* __restrict__ cs,
                                          int N, int K, int bx, int by, float* sm)
{
    float* As = sm;
    float* Bs = sm + GSTAGES * TS_STRIDE;

    const int tid  = threadIdx.x;
    const int lane = tid & 31;
    const int warp = tid >> 5;
    const int wm = (warp & 1) * 64;
    const int wn = (warp >> 1) * 32;
    const int lr = lane >> 2;
    const int lc = lane & 3;
    const int lrow  = lane & 15;
    const int lkoff = (lane >> 4) * 4;

    const int r0 = tid >> 3;
    const int c4 = (tid & 7) << 2;
    const float* Abase = A  + (size_t)(by * 128 + r0) * K + c4;
    const float* Bbase = Bt + (size_t)(bx * 128 + r0) * K + c4;

    const int kt = K >> 5;

    #pragma unroll
    for (int s = 0; s < GSTAGES - 1; s++) {
        #pragma unroll
        for (int j = 0; j < 4; j++) {
            cpasync16(As + s * TS_STRIDE + (r0 + 32 * j) * 36 + c4,
                      Abase + (size_t)(32 * j) * K + s * 32);
            cpasync16(Bs + s * TS_STRIDE + (r0 + 32 * j) * 36 + c4,
                      Bbase + (size_t)(32 * j) * K + s * 32);
        }
        CP_COMMIT();
    }

    float acc[4][4][4];
    #pragma unroll
    for (int mt = 0; mt < 4; mt++)
        #pragma unroll
        for (int nt = 0; nt < 4; nt++)
            #pragma unroll
            for (int r = 0; r < 4; r++) acc[mt][nt][r] = 0.0f;

    int cb = 0, pb = GSTAGES - 1;
    for (int it = 0; it < kt; it++) {
        CP_WAIT(GSTAGES - 2);
        __syncthreads();

        int nx = it + GSTAGES - 1;
        if (nx < kt) {
            #pragma unroll
            for (int j = 0; j < 4; j++) {
                cpasync16(As + pb * TS_STRIDE + (r0 + 32 * j) * 36 + c4,
                          Abase + (size_t)(32 * j) * K + nx * 32);
                cpasync16(Bs + pb * TS_STRIDE + (r0 + 32 * j) * 36 + c4,
                          Bbase + (size_t)(32 * j) * K + nx * 32);
            }
        }
        CP_COMMIT();
        if (++pb == GSTAGES) pb = 0;

        const float* Asc = As + cb * TS_STRIDE;
        const float* Bsc = Bs + cb * TS_STRIDE;
        if (++cb == GSTAGES) cb = 0;

        #pragma unroll
        for (int kb = 0; kb < 4; kb++) {
            unsigned af[4][4];
            #pragma unroll
            for (int mt = 0; mt < 4; mt++) {
                unsigned addr = (unsigned)__cvta_generic_to_shared(
                    Asc + (wm + mt * 16 + lrow) * 36 + kb * 8 + lkoff);
                ldmx4(af[mt][0], af[mt][1], af[mt][2], af[mt][3], addr);
            }
            unsigned bf[4][2];
            #pragma unroll
            for (int nt2 = 0; nt2 < 2; nt2++) {
                unsigned q0, q1, q2, q3;
                unsigned addr = (unsigned)__cvta_generic_to_shared(
                    Bsc + (wn + nt2 * 16 + lrow) * 36 + kb * 8 + lkoff);
                ldmx4(q0, q1, q2, q3, addr);
                bf[nt2 * 2 + 0][0] = q0; bf[nt2 * 2 + 0][1] = q2;
                bf[nt2 * 2 + 1][0] = q1; bf[nt2 * 2 + 1][1] = q3;
            }
            #pragma unroll
            for (int mt = 0; mt < 4; mt++)
                #pragma unroll
                for (int nt = 0; nt < 4; nt++)
                    mma_tf32(acc[mt][nt], af[mt], bf[nt][0], bf[nt][1]);
        }
    }

    if (ROPE && (wn & 32) == 0) {
        #pragma unroll
        for (int mt = 0; mt < 4; mt++) {
            #pragma unroll
            for (int half = 0; half < 2; half++) {
                int rr = by * 128 + wm + mt * 16 + lr + half * 8;
                int t = rr & (TT - 1);
                #pragma unroll
                for (int nt2 = 0; nt2 < 2; nt2++) {
                    #pragma unroll
                    for (int j = 0; j < 2; j++) {
                        int i = nt2 * 8 + 2 * lc + j;
                        float2 cv = cs[t * 16 + i];
                        float x1 = acc[mt][nt2][half * 2 + j];
                        float x2 = acc[mt][nt2 + 2][half * 2 + j];
                        acc[mt][nt2][half * 2 + j]     = x1 * cv.x - x2 * cv.y;
                        acc[mt][nt2 + 2][half * 2 + j] = x2 * cv.x + x1 * cv.y;
                    }
                }
            }
        }
    }

    #pragma unroll
    for (int mt = 0; mt < 4; mt++) {
        #pragma unroll
        for (int nt = 0; nt < 4; nt++) {
            int row = by * 128 + wm + mt * 16 + lr;
            int col = bx * 128 + wn + nt * 8 + 2 * lc;
            #pragma unroll
            for (int half = 0; half < 2; half++) {
                int r = row + half * 8;
                size_t off = (size_t)r * N + col;
                float v0 = acc[mt][nt][half * 2 + 0];
                float v1 = acc[mt][nt][half * 2 + 1];
                if (EPI == 2 || EPI == 3) { v0 += bias[col]; v1 += bias[col + 1]; }
                if (EPI == 2) { v0 = gelu_tanh(v0); v1 = gelu_tanh(v1); }
                if (EPI == 1 || EPI == 3) { v0 += resid[off]; v1 += resid[off + 1]; }
                if (RND) { v0 = f2tf32f(v0); v1 = f2tf32f(v1); }
                *(float2*)(C + off) = make_float2(v0, v1);
            }
        }
    }
}

template<int EPI, bool RND>
__global__ __launch_bounds__(256, 2)
void tgemm_kernel(const float* __restrict__ A, const float* __restrict__ Bt,
                  float* __restrict__ C, const float* __restrict__ bias,
                  const float* __restrict__ resid, int N, int K)
{
    extern __shared__ float smg[];
    gemm_core<EPI, RND, false>(A, Bt, C, bias, resid, nullptr, N, K,
                               blockIdx.x, blockIdx.y, smg);
}

__global__ __launch_bounds__(256, 2)
void qkv_kernel(const float* __restrict__ y, const float* __restrict__ xn,
                const float* __restrict__ wr, const float2* __restrict__ cs,
                float* __restrict__ q, float* __restrict__ k, float* __restrict__ v)
{
    extern __shared__ float smg[];
    int z = blockIdx.z;
    const float* A = (z == 2) ? xn : y;
    const float* B = wr + (size_t)z * 1024 * 1024;
    float*       C = (z == 0) ? q : (z == 1) ? k : v;
    gemm_core<0, true, true>(A, B, C, nullptr, nullptr, cs, 1024, 1024,
                             blockIdx.x, blockIdx.y, smg);
}

// ---------------- tf32 mma flash attention, BM=128, BN=64, paired q-tiles ------
#define AT_QS 0
#define AT_KS (128*68)
#define AT_VS (AT_KS + 64*68)
#define AT_PS (AT_VS + 64*72)
#define ATTN_SMEM_FLOATS (AT_PS + 128*68)
#define ATTN_SMEM_BYTES (ATTN_SMEM_FLOATS*4)
#define NQT (TT/128)   // 16

__global__ __launch_bounds__(256, 2)
void attn_kernel(const float* __restrict__ Q, const float* __restrict__ Kk,
                 const float* __restrict__ V, float* __restrict__ O)
{
    extern __shared__ float sm[];

    const int bh = blockIdx.y;
    const int b = bh >> 4, h = bh & 15;
    const size_t ld = DD;
    const float* Qb = Q  + (size_t)b * TT * ld + h * 64;
    const float* Kb = Kk + (size_t)b * TT * ld + h * 64;
    const float* Vb = V  + (size_t)b * TT * ld + h * 64;
    float*       Ob = O  + (size_t)b * TT * ld + h * 64;

    const int tid  = threadIdx.x;
    const int lane = tid & 31;
    const int warp = tid >> 5;
    const int lr = lane >> 2;
    const int lc = lane & 3;
    const int lrow  = lane & 15;
    const int lkoff = (lane >> 4) * 4;

    const int ldr0 = tid >> 4;
    const int ldc4 = (tid & 15) << 2;

    #pragma unroll 1
    for (int pass = 0; pass < 2; pass++) {
        const int qt = pass ? (NQT - 1 - blockIdx.x) : blockIdx.x;
        const int nkt = 2 * qt + 2;
        const int row_min = qt * 128 + warp * 16;

        __syncthreads();

        #pragma unroll
        for (int j = 0; j < 4; j++) {
            int r = ldr0 + j * 16;
            cpasync16(&sm[AT_KS + r * 68 + ldc4], Kb + (size_t)r * ld + ldc4);
        }
        CP_COMMIT();
        #pragma unroll
        for (int j = 0; j < 4; j++) {
            int r = ldr0 + j * 16;
            cpasync16(&sm[AT_VS + r * 72 + ldc4], Vb + (size_t)r * ld + ldc4);
        }
        CP_COMMIT();

        for (int i = tid; i < 128 * 16; i += 256) {
            int r = i >> 4, c4 = (i & 15) << 2;
            float4 qv = *(const float4*)(Qb + (size_t)(qt * 128 + r) * ld + c4);
            qv.x *= 0.125f; qv.y *= 0.125f; qv.z *= 0.125f; qv.w *= 0.125f;
            *(float4*)&sm[AT_QS + r * 68 + c4] = qv;
        }

        float m_i[2] = {-1e30f, -1e30f};
        float l_i[2] = {0.0f, 0.0f};
        float o[8][4];
        #pragma unroll
        for (int nt = 0; nt < 8; nt++)
            #pragma unroll
            for (int r = 0; r < 4; r++) o[nt][r] = 0.0f;

        for (int kt = 0; kt < nkt; kt++) {
            const bool active = (kt * 64 <= row_min + 15);
            float s[8][4];

            CP_WAIT(1);
            __syncthreads();

            if (active) {
                #pragma unroll
                for (int nt = 0; nt < 8; nt++)
                    #pragma unroll
                    for (int r = 0; r < 4; r++) s[nt][r] = 0.0f;

                #pragma unroll
                for (int kb = 0; kb < 8; kb++) {
                    unsigned af[4];
                    unsigned qaddr = (unsigned)__cvta_generic_to_shared(
                        &sm[AT_QS + (warp * 16 + lrow) * 68 + kb * 8 + lkoff]);
                    ldmx4(af[0], af[1], af[2], af[3], qaddr);
                    // K fragments: 4 x ldmx4, each covers 16 seq rows (2 nt tiles)
                    unsigned bf[8][2];
                    #pragma unroll
                    for (int nt2 = 0; nt2 < 4; nt2++) {
                        unsigned q0, q1, q2, q3;
                        unsigned kaddr = (unsigned)__cvta_generic_to_shared(
                            &sm[AT_KS + (nt2 * 16 + lrow) * 68 + kb * 8 + lkoff]);
                        ldmx4(q0, q1, q2, q3, kaddr);
                        bf[nt2 * 2 + 0][0] = q0; bf[nt2 * 2 + 0][1] = q2;
                        bf[nt2 * 2 + 1][0] = q1; bf[nt2 * 2 + 1][1] = q3;
                    }
                    #pragma unroll
                    for (int nt = 0; nt < 8; nt++)
                        mma_tf32(s[nt], af, bf[nt][0], bf[nt][1]);
                }

                if (kt * 64 + 63 > row_min) {
                    #pragma unroll
                    for (int nt = 0; nt < 8; nt++)
                        #pragma unroll
                        for (int r = 0; r < 4; r++) {
                            int col = kt * 64 + nt * 8 + 2 * lc + (r & 1);
                            int row = row_min + lr + 8 * (r >> 1);
                            if (col > row) s[nt][r] = -1e30f;
                        }
                }

                #pragma unroll
                for (int h2 = 0; h2 < 2; h2++) {
                    float rm = -1e30f;
                    #pragma unroll
                    for (int nt = 0; nt < 8; nt++)
                        rm = fmaxf(rm, fmaxf(s[nt][2*h2], s[nt][2*h2+1]));
                    rm = fmaxf(rm, __shfl_xor_sync(0xffffffffu, rm, 1));
                    rm = fmaxf(rm, __shfl_xor_sync(0xffffffffu, rm, 2));
                    float mn = fmaxf(m_i[h2], rm);
                    float alpha = __expf(m_i[h2] - mn);
                    m_i[h2] = mn;
                    float rs = 0.0f;
                    #pragma unroll
                    for (int nt = 0; nt < 8; nt++) {
                        float p0 = __expf(s[nt][2*h2]   - mn);
                        float p1 = __expf(s[nt][2*h2+1] - mn);
                        s[nt][2*h2]   = p0;
                        s[nt][2*h2+1] = p1;
                        rs += p0 + p1;
                    }
                    rs += __shfl_xor_sync(0xffffffffu, rs, 1);
                    rs += __shfl_xor_sync(0xffffffffu, rs, 2);
                    l_i[h2] = l_i[h2] * alpha + rs;
                    #pragma unroll
                    for (int nt = 0; nt < 8; nt++) {
                        o[nt][2*h2]   *= alpha;
                        o[nt][2*h2+1] *= alpha;
                    }
                }
            }

            __syncthreads();
            if (kt + 1 < nkt) {
                #pragma unroll
                for (int j = 0; j < 4; j++) {
                    int r = ldr0 + j * 16;
                    cpasync16(&sm[AT_KS + r * 68 + ldc4],
                              Kb + (size_t)((kt + 1) * 64 + r) * ld + ldc4);
                }
            }
            CP_COMMIT();

            CP_WAIT(1);
            __syncthreads();

            if (active) {
                #pragma unroll
                for (int nt = 0; nt < 8; nt++)
                    #pragma unroll
                    for (int r = 0; r < 4; r++) {
                        int row = warp * 16 + lr + 8 * (r >> 1);
                        int col = nt * 8 + 2 * lc + (r & 1);
                        sm[AT_PS + row * 68 + col] = f2tf32f(s[nt][r]);
                    }
                __syncwarp();

                #pragma unroll
                for (int kb = 0; kb < 8; kb++) {
                    unsigned af[4];
                    unsigned paddr = (unsigned)__cvta_generic_to_shared(
                        &sm[AT_PS + (warp * 16 + lrow) * 68 + kb * 8 + lkoff]);
                    ldmx4(af[0], af[1], af[2], af[3], paddr);
                    #pragma unroll
                    for (int nt = 0; nt < 8; nt++) {
                        unsigned b0 = __float_as_uint(sm[AT_VS + (kb * 8 + lc)     * 72 + nt * 8 + lr]);
                        unsigned b1 = __float_as_uint(sm[AT_VS + (kb * 8 + lc + 4) * 72 + nt * 8 + lr]);
                        mma_tf32(o[nt], af, b0, b1);
                    }
                }
            }

            __syncthreads();
            if (kt + 1 < nkt) {
                #pragma unroll
                for (int j = 0; j < 4; j++) {
                    int r = ldr0 + j * 16;
                    cpasync16(&sm[AT_VS + r * 72 + ldc4],
                              Vb + (size_t)((kt + 1) * 64 + r) * ld + ldc4);
                }
            }
            CP_COMMIT();
        }

        #pragma unroll
        for (int h2 = 0; h2 < 2; h2++) {
            float inv = 1.0f / l_i[h2];
            int row = qt * 128 + warp * 16 + lr + 8 * h2;
            #pragma unroll
            for (int nt = 0; nt < 8; nt++) {
                int col = nt * 8 + 2 * lc;
                *(float2*)(Ob + (size_t)row * ld + col) =
                    make_float2(f2tf32f(o[nt][2*h2] * inv), f2tf32f(o[nt][2*h2+1] * inv));
            }
        }
    }
}

// ---------------- launch ----------------
extern "C" void kernel_launch(void* const* d_in, const int* in_sizes, int n_in,
                              void* d_out, int out_size)
{
    const float* x       = (const float*)d_in[0];
    const float* w_q     = (const float*)d_in[1];
    const float* w_k     = (const float*)d_in[2];
    const float* w_v     = (const float*)d_in[3];
    const float* w_o     = (const float*)d_in[4];
    const float* alpha_p = (const float*)d_in[5];
    const float* delta_p = (const float*)d_in[6];
    const float* beta    = (const float*)d_in[7];
    const float* eta     = (const float*)d_in[8];
    const float* g1      = (const float*)d_in[9];
    const float* g2      = (const float*)d_in[10];
    const float* w_in    = (const float*)d_in[11];
    const float* b_in    = (const float*)d_in[12];
    const float* w_out   = (const float*)d_in[13];
    const float* b_out   = (const float*)d_in[14];
    float* out = (float*)d_out;

    float *xn, *y, *q, *k, *v, *ao, *x1, *xn2, *hb, *wr, *e1, *e2;
    float2* cs;
    cudaGetSymbolAddress((void**)&xn,  g_xn);
    cudaGetSymbolAddress((void**)&y,   g_y);
    cudaGetSymbolAddress((void**)&q,   g_q);
    cudaGetSymbolAddress((void**)&k,   g_k);
    cudaGetSymbolAddress((void**)&v,   g_v);
    cudaGetSymbolAddress((void**)&ao,  g_ao);
    cudaGetSymbolAddress((void**)&x1,  g_x1);
    cudaGetSymbolAddress((void**)&xn2, g_xn2);
    cudaGetSymbolAddress((void**)&hb,  g_hb);
    cudaGetSymbolAddress((void**)&wr,  g_w);
    cudaGetSymbolAddress((void**)&e1,  g_e1);
    cudaGetSymbolAddress((void**)&e2,  g_e2);
    cudaGetSymbolAddress((void**)&cs,  g_cs);

    cudaFuncSetAttribute(attn_kernel, cudaFuncAttributeMaxDynamicSharedMemorySize,
                         ATTN_SMEM_BYTES);
    cudaFuncSetAttribute(qkv_kernel, cudaFuncAttributeMaxDynamicSharedMemorySize, SMEM_GEMM);
    cudaFuncSetAttribute((const void*)tgemm_kernel<1,false>, cudaFuncAttributeMaxDynamicSharedMemorySize, SMEM_GEMM);
    cudaFuncSetAttribute((const void*)tgemm_kernel<2,true>,  cudaFuncAttributeMaxDynamicSharedMemorySize, SMEM_GEMM);
    cudaFuncSetAttribute((const void*)tgemm_kernel<3,false>, cudaFuncAttributeMaxDynamicSharedMemorySize, SMEM_GEMM);

    wtrans_kernel<<<12288, dim3(32, 8)>>>(w_q, w_k, w_v, w_o, w_in, w_out, wr);
    cstab_kernel<<<(TT * 16) / 256, 256>>>(cs);

    rmsnorm_kernel<<<BT, 256>>>(x, g1, xn, 1);

    ema1_kernel<<<(BB * EG * DD) / 256, 256>>>(xn, alpha_p, delta_p, beta, e1);
    ema2_kernel<<<(BB * 16 * DD) / 256, 256>>>(e1, alpha_p, delta_p, e2);
    ema3_kernel<<<(BB * EG * DD) / 256, 256>>>(xn, alpha_p, delta_p, beta, eta, e2, y);

    qkv_kernel<<<dim3(1024 / 128, BT / 128, 3), 256, SMEM_GEMM>>>(y, xn, wr, cs, q, k, v);

    attn_kernel<<<dim3(NQT / 2, BB * HH), 256, ATTN_SMEM_BYTES>>>(q, k, v, ao);

    dim3 gN1024(1024 / 128, BT / 128);
    tgemm_kernel<1,false><<<gN1024, 256, SMEM_GEMM>>>(ao, wr + 3 * 1024 * 1024, x1,
                                                      nullptr, x, 1024, 1024);

    rmsnorm_kernel<<<BT, 256>>>(x1, g2, xn2, 1);

    dim3 gN4096(4096 / 128, BT / 128);
    tgemm_kernel<2,true><<<gN4096, 256, SMEM_GEMM>>>(xn2, wr + 4 * 1024 * 1024, hb,
                                                     b_in, nullptr, 4096, 1024);
    tgemm_kernel<3,false><<<gN1024, 256, SMEM_GEMM>>>(hb, wr + 8 * 1024 * 1024, out,
                                                      b_out, x1, 1024, 4096);
}

// round 16
// speedup vs baseline: 1.0006x; 1.0006x over previous
#include <cuda_runtime.h>
#include <math.h>

#define BB 2
#define TT 2048
#define DD 1024
#define HH 16
#define HIDD 4096
#define BT (BB*TT)   // 4096 rows

// ---------------- scratch ----------------
__device__ float g_xn [BB*TT*DD];
__device__ float g_y  [BB*TT*DD];
__device__ float g_q  [BB*TT*DD];
__device__ float g_k  [BB*TT*DD];
__device__ float g_v  [BB*TT*DD];
__device__ float g_ao [BB*TT*DD];
__device__ float g_x1 [BB*TT*DD];
__device__ float g_xn2[BB*TT*DD];
__device__ float g_hb [BB*TT*HIDD];
__device__ float g_w  [12*1024*1024];   // rounded TRANSPOSED weights [n][k]
__device__ float g_e1 [BB*64*16*DD];    // ema chunk h_end   [b][g][n][d]
__device__ float g_e2 [BB*64*16*DD];    // ema chunk h_start [b][g][n][d]
__device__ float2 g_cs[TT*16];          // rope cos/sin table [t][i]

// ---------------- helpers ----------------
__device__ __forceinline__ unsigned f2tf32(float x)
{
    unsigned r;
    asm("cvt.rna.tf32.f32 %0, %1;" : "=r"(r) : "f"(x));
    return r;
}
__device__ __forceinline__ float f2tf32f(float x) { return __uint_as_float(f2tf32(x)); }
__device__ __forceinline__ float4 cvt4(float4 v)
{
    return make_float4(f2tf32f(v.x), f2tf32f(v.y), f2tf32f(v.z), f2tf32f(v.w));
}

__device__ __forceinline__ void ldmx4(unsigned& a0, unsigned& a1, unsigned& a2, unsigned& a3,
                                      unsigned addr)
{
    asm volatile("ldmatrix.sync.aligned.m8n8.x4.shared.b16 {%0,%1,%2,%3}, [%4];"
                 : "=r"(a0), "=r"(a1), "=r"(a2), "=r"(a3) : "r"(addr));
}
__device__ __forceinline__ void mma_tf32(float* d, const unsigned* a, unsigned b0, unsigned b1)
{
    asm volatile(
        "mma.sync.aligned.m16n8k8.row.col.f32.tf32.tf32.f32 "
        "{%0,%1,%2,%3}, {%4,%5,%6,%7}, {%8,%9}, {%0,%1,%2,%3};\n"
        : "+f"(d[0]), "+f"(d[1]), "+f"(d[2]), "+f"(d[3])
        : "r"(a[0]), "r"(a[1]), "r"(a[2]), "r"(a[3]), "r"(b0), "r"(b1));
}
__device__ __forceinline__ void cpasync16(void* smem, const void* gmem)
{
    unsigned s = (unsigned)__cvta_generic_to_shared(smem);
    asm volatile("cp.async.cg.shared.global [%0], [%1], 16;" :: "r"(s), "l"(gmem));
}
#define CP_COMMIT() asm volatile("cp.async.commit_group;")
#define CP_WAIT(n)  asm volatile("cp.async.wait_group %0;" :: "n"(n))

// ---------------- weight transpose + tf32 round  (+ rope table in tail blocks) --
__global__ void wtrans_kernel(const float* __restrict__ wq, const float* __restrict__ wk,
                              const float* __restrict__ wv, const float* __restrict__ wo,
                              const float* __restrict__ win, const float* __restrict__ wout,
                              float* __restrict__ dst, float2* __restrict__ cs)
{
    __shared__ float tile[32][33];
    int t = blockIdx.x;
    if (t >= 12288) {   // rope cos/sin table: 128 tail blocks cover TT*16 entries
        int idx = (t - 12288) * 256 + threadIdx.y * 32 + threadIdx.x;
        int i = idx & 15;
        int tt = idx >> 4;
        double fd = pow(10000.0, -(double)i / 16.0);
        float freq = (float)fd;
        float ang = (float)tt * freq;
        double da = (double)ang;
        cs[idx] = make_float2((float)cos(da), (float)sin(da));
        return;
    }
    const float* src; int K, N; size_t doff;
    if (t < 4096) {
        int m = t >> 10; t &= 1023;
        src = (m == 0) ? wq : (m == 1) ? wk : (m == 2) ? wv : wo;
        K = 1024; N = 1024; doff = (size_t)m * 1024 * 1024;
    } else if (t < 8192) {
        t -= 4096; src = win;  K = 1024; N = 4096; doff = (size_t)4 * 1024 * 1024;
    } else {
        t -= 8192; src = wout; K = 4096; N = 1024; doff = (size_t)8 * 1024 * 1024;
    }
    int ktiles = K >> 5;
    int k0 = (t % ktiles) << 5;
    int n0 = (t / ktiles) << 5;
    int tx = threadIdx.x, ty = threadIdx.y;   // (32, 8)
    #pragma unroll
    for (int j = 0; j < 4; j++)
        tile[ty + j * 8][tx] = src[(size_t)(k0 + ty + j * 8) * N + n0 + tx];
    __syncthreads();
    #pragma unroll
    for (int j = 0; j < 4; j++)
        dst[doff + (size_t)(n0 + ty + j * 8) * K + k0 + tx] = f2tf32f(tile[tx][ty + j * 8]);
}

// ---------------- rmsnorm ----------------
__global__ void rmsnorm_kernel(const float* __restrict__ x, const float* __restrict__ g,
                               float* __restrict__ out, int rnd)
{
    int row = blockIdx.x;
    int tid = threadIdx.x;
    const float4* xr = (const float4*)(x + (size_t)row * DD);
    float4 v = xr[tid];
    float s = v.x*v.x + v.y*v.y + v.z*v.z + v.w*v.w;
    #pragma unroll
    for (int o = 16; o; o >>= 1) s += __shfl_xor_sync(0xffffffffu, s, o);
    __shared__ float red[8];
    if ((tid & 31) == 0) red[tid >> 5] = s;
    __syncthreads();
    float tot = red[0]+red[1]+red[2]+red[3]+red[4]+red[5]+red[6]+red[7];
    float inv = rsqrtf(tot * (1.0f / (float)DD) + 1e-6f);
    const float4* gr = (const float4*)g;
    float4 gv = gr[tid];
    float4 o4;
    o4.x = gv.x * (v.x * inv);
    o4.y = gv.y * (v.y * inv);
    o4.z = gv.z * (v.z * inv);
    o4.w = gv.w * (v.w * inv);
    if (rnd) o4 = cvt4(o4);
    ((float4*)(out + (size_t)row * DD))[tid] = o4;
}

// ---------------- EMA chunked scan (G=64 chunks of 32 steps) ----------------
#define EG 64
#define ECH 32

__global__ void ema1_kernel(const float* __restrict__ xn,
                            const float* __restrict__ ap, const float* __restrict__ dp,
                            const float* __restrict__ beta,
                            float* __restrict__ hend)
{
    int idx = blockIdx.x * blockDim.x + threadIdx.x;   // 2^17
    int d = idx & 1023;
    int g = (idx >> 10) & (EG - 1);
    int b = idx >> 16;
    float dec[16], ab[16], h[16];
    #pragma unroll
    for (int n = 0; n < 16; n++) {
        int dn = d * 16 + n;
        float a   = 1.0f / (1.0f + expf(-ap[dn]));
        float ddv = 1.0f / (1.0f + expf(-dp[dn]));
        dec[n] = 1.0f - a * ddv;
        ab[n]  = a * beta[dn];
        h[n]   = 0.0f;
    }
    const float* xp = xn + ((size_t)b * TT + g * ECH) * DD + d;
    #pragma unroll 4
    for (int t = 0; t < ECH; t++) {
        float u = xp[(size_t)t * DD];
        #pragma unroll
        for (int n = 0; n < 16; n++)
            h[n] = fmaf(dec[n], h[n], ab[n] * u);
    }
    size_t base = ((size_t)b * EG + g) * 16 * DD + d;
    #pragma unroll
    for (int n = 0; n < 16; n++)
        hend[base + (size_t)n * DD] = h[n];
}

__global__ void ema2_kernel(const float* __restrict__ hend,
                            const float* __restrict__ ap, const float* __restrict__ dp,
                            float* __restrict__ hstart)
{
    int idx = blockIdx.x * blockDim.x + threadIdx.x;   // 2^15
    int d = idx & 1023;
    int n = (idx >> 10) & 15;
    int b = idx >> 14;
    int dn = d * 16 + n;
    float a   = 1.0f / (1.0f + expf(-ap[dn]));
    float ddv = 1.0f / (1.0f + expf(-dp[dn]));
    float dec = 1.0f - a * ddv;
    float dch = dec;
    #pragma unroll
    for (int j = 0; j < 5; j++) dch *= dch;            // dec^32
    size_t base = ((size_t)b * EG * 16 + n) * DD + d;
    float H = 0.0f;
    #pragma unroll
    for (int gg = 0; gg < EG; gg += 16) {
        float hv[16];
        #pragma unroll
        for (int j = 0; j < 16; j++)
            hv[j] = hend[base + (size_t)(gg + j) * 16 * DD];
        #pragma unroll
        for (int j = 0; j < 16; j++) {
            hstart[base + (size_t)(gg + j) * 16 * DD] = H;
            H = fmaf(dch, H, hv[j]);
        }
    }
}

__global__ void ema3_kernel(const float* __restrict__ xn,
                            const float* __restrict__ ap, const float* __restrict__ dp,
                            const float* __restrict__ beta, const float* __restrict__ eta,
                            const float* __restrict__ hstart,
                            float* __restrict__ y)
{
    int idx = blockIdx.x * blockDim.x + threadIdx.x;   // 2^17
    int d = idx & 1023;
    int g = (idx >> 10) & (EG - 1);
    int b = idx >> 16;
    float dec[16], ab[16], et[16], h[16];
    #pragma unroll
    for (int n = 0; n < 16; n++) {
        int dn = d * 16 + n;
        float a   = 1.0f / (1.0f + expf(-ap[dn]));
        float ddv = 1.0f / (1.0f + expf(-dp[dn]));
        dec[n] = 1.0f - a * ddv;
        ab[n]  = a * beta[dn];
        et[n]  = eta[dn];
        h[n]   = hstart[(((size_t)b * EG + g) * 16 + n) * DD + d];
    }
    const float* xp = xn + ((size_t)b * TT + g * ECH) * DD + d;
    float*       yp = y  + ((size_t)b * TT + g * ECH) * DD + d;
    #pragma unroll 4
    for (int t = 0; t < ECH; t++) {
        float u = xp[(size_t)t * DD];
        float s0 = 0.f, s1 = 0.f, s2 = 0.f, s3 = 0.f;
        #pragma unroll
        for (int n = 0; n < 16; n += 4) {
            h[n]   = fmaf(dec[n],   h[n],   ab[n]   * u);
            h[n+1] = fmaf(dec[n+1], h[n+1], ab[n+1] * u);
            h[n+2] = fmaf(dec[n+2], h[n+2], ab[n+2] * u);
            h[n+3] = fmaf(dec[n+3], h[n+3], ab[n+3] * u);
            s0 = fmaf(et[n],   h[n],   s0);
            s1 = fmaf(et[n+1], h[n+1], s1);
            s2 = fmaf(et[n+2], h[n+2], s2);
            s3 = fmaf(et[n+3], h[n+3], s3);
        }
        yp[(size_t)t * DD] = f2tf32f((s0 + s1) + (s2 + s3));
    }
}

// ---------------- tf32 GEMM core: 128x128xK32, cp.async 3-stage, all-ldmatrix ---
__device__ __forceinline__ float gelu_tanh(float x)
{
    float z = 0.7978845608028654f * (x + 0.044715f * x * x * x);
    float e = __expf(2.0f * z);
    float t = 1.0f - 2.0f / (e + 1.0f);
    return 0.5f * x * (1.0f + t);
}

#define GSTAGES 3
#define TS_STRIDE (128*36)
#define SMEM_GEMM ((GSTAGES * 2 * TS_STRIDE) * 4)

template<int EPI, bool RND, bool ROPE>
__device__ __forceinline__ void gemm_core(const float* __restrict__ A,
                                          const float* __restrict__ Bt,
                                          float* __restrict__ C,
                                          const float* __restrict__ bias,
                                          const float* __restrict__ resid,
                                          const float2* __restrict__ cs,
                                          int N, int K, int bx, int by, float* sm)
{
    float* As = sm;
    float* Bs = sm + GSTAGES * TS_STRIDE;

    const int tid  = threadIdx.x;
    const int lane = tid & 31;
    const int warp = tid >> 5;
    const int wm = (warp & 1) * 64;
    const int wn = (warp >> 1) * 32;
    const int lr = lane >> 2;
    const int lc = lane & 3;
    const int lrow  = lane & 15;
    const int lkoff = (lane >> 4) * 4;

    const int r0 = tid >> 3;
    const int c4 = (tid & 7) << 2;
    const float* Abase = A  + (size_t)(by * 128 + r0) * K + c4;
    const float* Bbase = Bt + (size_t)(bx * 128 + r0) * K + c4;

    const int kt = K >> 5;

    #pragma unroll
    for (int s = 0; s < GSTAGES - 1; s++) {
        #pragma unroll
        for (int j = 0; j < 4; j++) {
            cpasync16(As + s * TS_STRIDE + (r0 + 32 * j) * 36 + c4,
                      Abase + (size_t)(32 * j) * K + s * 32);
            cpasync16(Bs + s * TS_STRIDE + (r0 + 32 * j) * 36 + c4,
                      Bbase + (size_t)(32 * j) * K + s * 32);
        }
        CP_COMMIT();
    }

    float acc[4][4][4];
    #pragma unroll
    for (int mt = 0; mt < 4; mt++)
        #pragma unroll
        for (int nt = 0; nt < 4; nt++)
            #pragma unroll
            for (int r = 0; r < 4; r++) acc[mt][nt][r] = 0.0f;

    int cb = 0, pb = GSTAGES - 1;
    for (int it = 0; it < kt; it++) {
        CP_WAIT(GSTAGES - 2);
        __syncthreads();

        int nx = it + GSTAGES - 1;
        if (nx < kt) {
            #pragma unroll
            for (int j = 0; j < 4; j++) {
                cpasync16(As + pb * TS_STRIDE + (r0 + 32 * j) * 36 + c4,
                          Abase + (size_t)(32 * j) * K + nx * 32);
                cpasync16(Bs + pb * TS_STRIDE + (r0 + 32 * j) * 36 + c4,
                          Bbase + (size_t)(32 * j) * K + nx * 32);
            }
        }
        CP_COMMIT();
        if (++pb == GSTAGES) pb = 0;

        const float* Asc = As + cb * TS_STRIDE;
        const float* Bsc = Bs + cb * TS_STRIDE;
        if (++cb == GSTAGES) cb = 0;

        #pragma unroll
        for (int kb = 0; kb < 4; kb++) {
            unsigned af[4][4];
            #pragma unroll
            for (int mt = 0; mt < 4; mt++) {
                unsigned addr = (unsigned)__cvta_generic_to_shared(
                    Asc + (wm + mt * 16 + lrow) * 36 + kb * 8 + lkoff);
                ldmx4(af[mt][0], af[mt][1], af[mt][2], af[mt][3], addr);
            }
            unsigned bf[4][2];
            #pragma unroll
            for (int nt2 = 0; nt2 < 2; nt2++) {
                unsigned q0, q1, q2, q3;
                unsigned addr = (unsigned)__cvta_generic_to_shared(
                    Bsc + (wn + nt2 * 16 + lrow) * 36 + kb * 8 + lkoff);
                ldmx4(q0, q1, q2, q3, addr);
                bf[nt2 * 2 + 0][0] = q0; bf[nt2 * 2 + 0][1] = q2;
                bf[nt2 * 2 + 1][0] = q1; bf[nt2 * 2 + 1][1] = q3;
            }
            #pragma unroll
            for (int mt = 0; mt < 4; mt++)
                #pragma unroll
                for (int nt = 0; nt < 4; nt++)
                    mma_tf32(acc[mt][nt], af[mt], bf[nt][0], bf[nt][1]);
        }
    }

    if (ROPE && (wn & 32) == 0) {
        #pragma unroll
        for (int mt = 0; mt < 4; mt++) {
            #pragma unroll
            for (int half = 0; half < 2; half++) {
                int rr = by * 128 + wm + mt * 16 + lr + half * 8;
                int t = rr & (TT - 1);
                #pragma unroll
                for (int nt2 = 0; nt2 < 2; nt2++) {
                    #pragma unroll
                    for (int j = 0; j < 2; j++) {
                        int i = nt2 * 8 + 2 * lc + j;
                        float2 cv = cs[t * 16 + i];
                        float x1 = acc[mt][nt2][half * 2 + j];
                        float x2 = acc[mt][nt2 + 2][half * 2 + j];
                        acc[mt][nt2][half * 2 + j]     = x1 * cv.x - x2 * cv.y;
                        acc[mt][nt2 + 2][half * 2 + j] = x2 * cv.x + x1 * cv.y;
                    }
                }
            }
        }
    }

    #pragma unroll
    for (int mt = 0; mt < 4; mt++) {
        #pragma unroll
        for (int nt = 0; nt < 4; nt++) {
            int row = by * 128 + wm + mt * 16 + lr;
            int col = bx * 128 + wn + nt * 8 + 2 * lc;
            #pragma unroll
            for (int half = 0; half < 2; half++) {
                int r = row + half * 8;
                size_t off = (size_t)r * N + col;
                float v0 = acc[mt][nt][half * 2 + 0];
                float v1 = acc[mt][nt][half * 2 + 1];
                if (EPI == 2 || EPI == 3) { v0 += bias[col]; v1 += bias[col + 1]; }
                if (EPI == 2) { v0 = gelu_tanh(v0); v1 = gelu_tanh(v1); }
                if (EPI == 1 || EPI == 3) { v0 += resid[off]; v1 += resid[off + 1]; }
                if (RND) { v0 = f2tf32f(v0); v1 = f2tf32f(v1); }
                *(float2*)(C + off) = make_float2(v0, v1);
            }
        }
    }
}

template<int EPI, bool RND>
__global__ __launch_bounds__(256, 2)
void tgemm_kernel(const float* __restrict__ A, const float* __restrict__ Bt,
                  float* __restrict__ C, const float* __restrict__ bias,
                  const float* __restrict__ resid, int N, int K)
{
    extern __shared__ float smg[];
    gemm_core<EPI, RND, false>(A, Bt, C, bias, resid, nullptr, N, K,
                               blockIdx.x, blockIdx.y, smg);
}

__global__ __launch_bounds__(256, 2)
void qkv_kernel(const float* __restrict__ y, const float* __restrict__ xn,
                const float* __restrict__ wr, const float2* __restrict__ cs,
                float* __restrict__ q, float* __restrict__ k, float* __restrict__ v)
{
    extern __shared__ float smg[];
    int z = blockIdx.z;
    const float* A = (z == 2) ? xn : y;
    const float* B = wr + (size_t)z * 1024 * 1024;
    float*       C = (z == 0) ? q : (z == 1) ? k : v;
    gemm_core<0, true, true>(A, B, C, nullptr, nullptr, cs, 1024, 1024,
                             blockIdx.x, blockIdx.y, smg);
}

// ---------------- tf32 mma flash attention, BM=128, BN=64, paired q-tiles ------
#define AT_QS 0
#define AT_KS (128*68)
#define AT_VS (AT_KS + 64*68)
#define AT_PS (AT_VS + 64*72)
#define ATTN_SMEM_FLOATS (AT_PS + 128*68)
#define ATTN_SMEM_BYTES (ATTN_SMEM_FLOATS*4)
#define NQT (TT/128)   // 16

__global__ __launch_bounds__(256, 2)
void attn_kernel(const float* __restrict__ Q, const float* __restrict__ Kk,
                 const float* __restrict__ V, float* __restrict__ O)
{
    extern __shared__ float sm[];

    const int bh = blockIdx.y;
    const int b = bh >> 4, h = bh & 15;
    const size_t ld = DD;
    const float* Qb = Q  + (size_t)b * TT * ld + h * 64;
    const float* Kb = Kk + (size_t)b * TT * ld + h * 64;
    const float* Vb = V  + (size_t)b * TT * ld + h * 64;
    float*       Ob = O  + (size_t)b * TT * ld + h * 64;

    const int tid  = threadIdx.x;
    const int lane = tid & 31;
    const int warp = tid >> 5;
    const int lr = lane >> 2;
    const int lc = lane & 3;
    const int lrow  = lane & 15;
    const int lkoff = (lane >> 4) * 4;

    const int ldr0 = tid >> 4;
    const int ldc4 = (tid & 15) << 2;

    #pragma unroll 1
    for (int pass = 0; pass < 2; pass++) {
        const int qt = pass ? (NQT - 1 - blockIdx.x) : blockIdx.x;
        const int nkt = 2 * qt + 2;
        const int row_min = qt * 128 + warp * 16;

        __syncthreads();

        #pragma unroll
        for (int j = 0; j < 4; j++) {
            int r = ldr0 + j * 16;
            cpasync16(&sm[AT_KS + r * 68 + ldc4], Kb + (size_t)r * ld + ldc4);
        }
        CP_COMMIT();
        #pragma unroll
        for (int j = 0; j < 4; j++) {
            int r = ldr0 + j * 16;
            cpasync16(&sm[AT_VS + r * 72 + ldc4], Vb + (size_t)r * ld + ldc4);
        }
        CP_COMMIT();

        for (int i = tid; i < 128 * 16; i += 256) {
            int r = i >> 4, c4 = (i & 15) << 2;
            float4 qv = *(const float4*)(Qb + (size_t)(qt * 128 + r) * ld + c4);
            qv.x *= 0.125f; qv.y *= 0.125f; qv.z *= 0.125f; qv.w *= 0.125f;
            *(float4*)&sm[AT_QS + r * 68 + c4] = qv;
        }

        float m_i[2] = {-1e30f, -1e30f};
        float l_i[2] = {0.0f, 0.0f};
        float o[8][4];
        #pragma unroll
        for (int nt = 0; nt < 8; nt++)
            #pragma unroll
            for (int r = 0; r < 4; r++) o[nt][r] = 0.0f;

        for (int kt = 0; kt < nkt; kt++) {
            const bool active = (kt * 64 <= row_min + 15);
            float s[8][4];

            CP_WAIT(1);            // K(kt) ready
            __syncthreads();

            if (active) {
                #pragma unroll
                for (int nt = 0; nt < 8; nt++)
                    #pragma unroll
                    for (int r = 0; r < 4; r++) s[nt][r] = 0.0f;

                #pragma unroll
                for (int kb = 0; kb < 8; kb++) {
                    unsigned af[4];
                    unsigned qaddr = (unsigned)__cvta_generic_to_shared(
                        &sm[AT_QS + (warp * 16 + lrow) * 68 + kb * 8 + lkoff]);
                    ldmx4(af[0], af[1], af[2], af[3], qaddr);
                    unsigned bf[8][2];
                    #pragma unroll
                    for (int nt2 = 0; nt2 < 4; nt2++) {
                        unsigned q0, q1, q2, q3;
                        unsigned kaddr = (unsigned)__cvta_generic_to_shared(
                            &sm[AT_KS + (nt2 * 16 + lrow) * 68 + kb * 8 + lkoff]);
                        ldmx4(q0, q1, q2, q3, kaddr);
                        bf[nt2 * 2 + 0][0] = q0; bf[nt2 * 2 + 0][1] = q2;
                        bf[nt2 * 2 + 1][0] = q1; bf[nt2 * 2 + 1][1] = q3;
                    }
                    #pragma unroll
                    for (int nt = 0; nt < 8; nt++)
                        mma_tf32(s[nt], af, bf[nt][0], bf[nt][1]);
                }
            }

            // ---- K consumers done; start K(kt+1) NOW so it overlaps softmax+PV --
            __syncthreads();
            if (kt + 1 < nkt) {
                #pragma unroll
                for (int j = 0; j < 4; j++) {
                    int r = ldr0 + j * 16;
                    cpasync16(&sm[AT_KS + r * 68 + ldc4],
                              Kb + (size_t)((kt + 1) * 64 + r) * ld + ldc4);
                }
            }
            CP_COMMIT();

            if (active) {
                if (kt * 64 + 63 > row_min) {
                    #pragma unroll
                    for (int nt = 0; nt < 8; nt++)
                        #pragma unroll
                        for (int r = 0; r < 4; r++) {
                            int col = kt * 64 + nt * 8 + 2 * lc + (r & 1);
                            int row = row_min + lr + 8 * (r >> 1);
                            if (col > row) s[nt][r] = -1e30f;
                        }
                }

                #pragma unroll
                for (int h2 = 0; h2 < 2; h2++) {
                    float rm = -1e30f;
                    #pragma unroll
                    for (int nt = 0; nt < 8; nt++)
                        rm = fmaxf(rm, fmaxf(s[nt][2*h2], s[nt][2*h2+1]));
                    rm = fmaxf(rm, __shfl_xor_sync(0xffffffffu, rm, 1));
                    rm = fmaxf(rm, __shfl_xor_sync(0xffffffffu, rm, 2));
                    float mn = fmaxf(m_i[h2], rm);
                    float alpha = __expf(m_i[h2] - mn);
                    m_i[h2] = mn;
                    float rs = 0.0f;
                    #pragma unroll
                    for (int nt = 0; nt < 8; nt++) {
                        float p0 = __expf(s[nt][2*h2]   - mn);
                        float p1 = __expf(s[nt][2*h2+1] - mn);
                        s[nt][2*h2]   = p0;
                        s[nt][2*h2+1] = p1;
                        rs += p0 + p1;
                    }
                    rs += __shfl_xor_sync(0xffffffffu, rs, 1);
                    rs += __shfl_xor_sync(0xffffffffu, rs, 2);
                    l_i[h2] = l_i[h2] * alpha + rs;
                    #pragma unroll
                    for (int nt = 0; nt < 8; nt++) {
                        o[nt][2*h2]   *= alpha;
                        o[nt][2*h2+1] *= alpha;
                    }
                }

                // ---- store P before the V wait (warp-private rows) ----
                #pragma unroll
                for (int nt = 0; nt < 8; nt++)
                    #pragma unroll
                    for (int r = 0; r < 4; r++) {
                        int row = warp * 16 + lr + 8 * (r >> 1);
                        int col = nt * 8 + 2 * lc + (r & 1);
                        sm[AT_PS + row * 68 + col] = f2tf32f(s[nt][r]);
                    }
            }

            CP_WAIT(1);            // V(kt) ready (K(kt+1) newest, may be in flight)
            __syncthreads();       // also orders Ps stores before Ps ldmatrix

            if (active) {
                #pragma unroll
                for (int kb = 0; kb < 8; kb++) {
                    unsigned af[4];
                    unsigned paddr = (unsigned)__cvta_generic_to_shared(
                        &sm[AT_PS + (warp * 16 + lrow) * 68 + kb * 8 + lkoff]);
                    ldmx4(af[0], af[1], af[2], af[3], paddr);
                    #pragma unroll
                    for (int nt = 0; nt < 8; nt++) {
                        unsigned b0 = __float_as_uint(sm[AT_VS + (kb * 8 + lc)     * 72 + nt * 8 + lr]);
                        unsigned b1 = __float_as_uint(sm[AT_VS + (kb * 8 + lc + 4) * 72 + nt * 8 + lr]);
                        mma_tf32(o[nt], af, b0, b1);
                    }
                }
            }

            __syncthreads();       // V consumers done
            if (kt + 1 < nkt) {
                #pragma unroll
                for (int j = 0; j < 4; j++) {
                    int r = ldr0 + j * 16;
                    cpasync16(&sm[AT_VS + r * 72 + ldc4],
                              Vb + (size_t)((kt + 1) * 64 + r) * ld + ldc4);
                }
            }
            CP_COMMIT();
        }

        #pragma unroll
        for (int h2 = 0; h2 < 2; h2++) {
            float inv = 1.0f / l_i[h2];
            int row = qt * 128 + warp * 16 + lr + 8 * h2;
            #pragma unroll
            for (int nt = 0; nt < 8; nt++) {
                int col = nt * 8 + 2 * lc;
                *(float2*)(Ob + (size_t)row * ld + col) =
                    make_float2(f2tf32f(o[nt][2*h2] * inv), f2tf32f(o[nt][2*h2+1] * inv));
            }
        }
    }
}

// ---------------- launch ----------------
extern "C" void kernel_launch(void* const* d_in, const int* in_sizes, int n_in,
                              void* d_out, int out_size)
{
    const float* x       = (const float*)d_in[0];
    const float* w_q     = (const float*)d_in[1];
    const float* w_k     = (const float*)d_in[2];
    const float* w_v     = (const float*)d_in[3];
    const float* w_o     = (const float*)d_in[4];
    const float* alpha_p = (const float*)d_in[5];
    const float* delta_p = (const float*)d_in[6];
    const float* beta    = (const float*)d_in[7];
    const float* eta     = (const float*)d_in[8];
    const float* g1      = (const float*)d_in[9];
    const float* g2      = (const float*)d_in[10];
    const float* w_in    = (const float*)d_in[11];
    const float* b_in    = (const float*)d_in[12];
    const float* w_out   = (const float*)d_in[13];
    const float* b_out   = (const float*)d_in[14];
    float* out = (float*)d_out;

    float *xn, *y, *q, *k, *v, *ao, *x1, *xn2, *hb, *wr, *e1, *e2;
    float2* cs;
    cudaGetSymbolAddress((void**)&xn,  g_xn);
    cudaGetSymbolAddress((void**)&y,   g_y);
    cudaGetSymbolAddress((void**)&q,   g_q);
    cudaGetSymbolAddress((void**)&k,   g_k);
    cudaGetSymbolAddress((void**)&v,   g_v);
    cudaGetSymbolAddress((void**)&ao,  g_ao);
    cudaGetSymbolAddress((void**)&x1,  g_x1);
    cudaGetSymbolAddress((void**)&xn2, g_xn2);
    cudaGetSymbolAddress((void**)&hb,  g_hb);
    cudaGetSymbolAddress((void**)&wr,  g_w);
    cudaGetSymbolAddress((void**)&e1,  g_e1);
    cudaGetSymbolAddress((void**)&e2,  g_e2);
    cudaGetSymbolAddress((void**)&cs,  g_cs);

    cudaFuncSetAttribute(attn_kernel, cudaFuncAttributeMaxDynamicSharedMemorySize,
                         ATTN_SMEM_BYTES);
    cudaFuncSetAttribute(qkv_kernel, cudaFuncAttributeMaxDynamicSharedMemorySize, SMEM_GEMM);
    cudaFuncSetAttribute((const void*)tgemm_kernel<1,false>, cudaFuncAttributeMaxDynamicSharedMemorySize, SMEM_GEMM);
    cudaFuncSetAttribute((const void*)tgemm_kernel<2,true>,  cudaFuncAttributeMaxDynamicSharedMemorySize, SMEM_GEMM);
    cudaFuncSetAttribute((const void*)tgemm_kernel<3,false>, cudaFuncAttributeMaxDynamicSharedMemorySize, SMEM_GEMM);

    wtrans_kernel<<<12288 + 128, dim3(32, 8)>>>(w_q, w_k, w_v, w_o, w_in, w_out, wr, cs);

    rmsnorm_kernel<<<BT, 256>>>(x, g1, xn, 1);

    ema1_kernel<<<(BB * EG * DD) / 256, 256>>>(xn, alpha_p, delta_p, beta, e1);
    ema2_kernel<<<(BB * 16 * DD) / 256, 256>>>(e1, alpha_p, delta_p, e2);
    ema3_kernel<<<(BB * EG * DD) / 256, 256>>>(xn, alpha_p, delta_p, beta, eta, e2, y);

    qkv_kernel<<<dim3(1024 / 128, BT / 128, 3), 256, SMEM_GEMM>>>(y, xn, wr, cs, q, k, v);

    attn_kernel<<<dim3(NQT / 2, BB * HH), 256, ATTN_SMEM_BYTES>>>(q, k, v, ao);

    dim3 gN1024(1024 / 128, BT / 128);
    tgemm_kernel<1,false><<<gN1024, 256, SMEM_GEMM>>>(ao, wr + 3 * 1024 * 1024, x1,
                                                      nullptr, x, 1024, 1024);

    rmsnorm_kernel<<<BT, 256>>>(x1, g2, xn2, 1);

    dim3 gN4096(4096 / 128, BT / 128);
    tgemm_kernel<2,true><<<gN4096, 256, SMEM_GEMM>>>(xn2, wr + 4 * 1024 * 1024, hb,
                                                     b_in, nullptr, 4096, 1024);
    tgemm_kernel<3,false><<<gN1024, 256, SMEM_GEMM>>>(hb, wr + 8 * 1024 * 1024, out,
                                                      b_out, x1, 1024, 4096);
}

// round 17
// speedup vs baseline: 1.2648x; 1.2640x over previous
#include <cuda_runtime.h>
#include <cuda_fp16.h>
#include <math.h>

#define BB 2
#define TT 2048
#define DD 1024
#define HH 16
#define HIDD 4096
#define BT (BB*TT)   // 4096 rows

// ---------------- scratch ----------------
__device__ float  g_xn  [BB*TT*DD];
__device__ __half g_xnh [BB*TT*DD];
__device__ __half g_yh  [BB*TT*DD];
__device__ float  g_q   [BB*TT*DD];
__device__ float  g_k   [BB*TT*DD];
__device__ float  g_v   [BB*TT*DD];
__device__ __half g_aoh [BB*TT*DD];
__device__ float  g_x1  [BB*TT*DD];
__device__ float  g_xn2 [BB*TT*DD];
__device__ __half g_xn2h[BB*TT*DD];
__device__ __half g_hbh [BB*TT*HIDD];
__device__ __half g_wh  [12*1024*1024];  // fp16 TRANSPOSED weights [n][k]
__device__ float  g_e1  [BB*64*16*DD];
__device__ float  g_e2  [BB*64*16*DD];
__device__ float2 g_cs  [TT*16];

// ---------------- helpers ----------------
__device__ __forceinline__ unsigned f2tf32(float x)
{
    unsigned r;
    asm("cvt.rna.tf32.f32 %0, %1;" : "=r"(r) : "f"(x));
    return r;
}
__device__ __forceinline__ float f2tf32f(float x) { return __uint_as_float(f2tf32(x)); }
__device__ __forceinline__ float4 cvt4(float4 v)
{
    return make_float4(f2tf32f(v.x), f2tf32f(v.y), f2tf32f(v.z), f2tf32f(v.w));
}

__device__ __forceinline__ void ldmx4(unsigned& a0, unsigned& a1, unsigned& a2, unsigned& a3,
                                      unsigned addr)
{
    asm volatile("ldmatrix.sync.aligned.m8n8.x4.shared.b16 {%0,%1,%2,%3}, [%4];"
                 : "=r"(a0), "=r"(a1), "=r"(a2), "=r"(a3) : "r"(addr));
}
__device__ __forceinline__ void mma_tf32(float* d, const unsigned* a, unsigned b0, unsigned b1)
{
    asm volatile(
        "mma.sync.aligned.m16n8k8.row.col.f32.tf32.tf32.f32 "
        "{%0,%1,%2,%3}, {%4,%5,%6,%7}, {%8,%9}, {%0,%1,%2,%3};\n"
        : "+f"(d[0]), "+f"(d[1]), "+f"(d[2]), "+f"(d[3])
        : "r"(a[0]), "r"(a[1]), "r"(a[2]), "r"(a[3]), "r"(b0), "r"(b1));
}
__device__ __forceinline__ void mma_f16(float* d, const unsigned* a, unsigned b0, unsigned b1)
{
    asm volatile(
        "mma.sync.aligned.m16n8k16.row.col.f32.f16.f16.f32 "
        "{%0,%1,%2,%3}, {%4,%5,%6,%7}, {%8,%9}, {%0,%1,%2,%3};\n"
        : "+f"(d[0]), "+f"(d[1]), "+f"(d[2]), "+f"(d[3])
        : "r"(a[0]), "r"(a[1]), "r"(a[2]), "r"(a[3]), "r"(b0), "r"(b1));
}
__device__ __forceinline__ void cpasync16(void* smem, const void* gmem)
{
    unsigned s = (unsigned)__cvta_generic_to_shared(smem);
    asm volatile("cp.async.cg.shared.global [%0], [%1], 16;" :: "r"(s), "l"(gmem));
}
#define CP_COMMIT() asm volatile("cp.async.commit_group;")
#define CP_WAIT(n)  asm volatile("cp.async.wait_group %0;" :: "n"(n))

// ---------------- weight transpose -> fp16 (+ rope table in tail blocks) --------
__global__ void wtrans_kernel(const float* __restrict__ wq, const float* __restrict__ wk,
                              const float* __restrict__ wv, const float* __restrict__ wo,
                              const float* __restrict__ win, const float* __restrict__ wout,
                              __half* __restrict__ dst, float2* __restrict__ cs)
{
    __shared__ float tile[32][33];
    int t = blockIdx.x;
    if (t >= 12288) {
        int idx = (t - 12288) * 256 + threadIdx.y * 32 + threadIdx.x;
        int i = idx & 15;
        int tt = idx >> 4;
        double fd = pow(10000.0, -(double)i / 16.0);
        float freq = (float)fd;
        float ang = (float)tt * freq;
        double da = (double)ang;
        cs[idx] = make_float2((float)cos(da), (float)sin(da));
        return;
    }
    const float* src; int K, N; size_t doff;
    if (t < 4096) {
        int m = t >> 10; t &= 1023;
        src = (m == 0) ? wq : (m == 1) ? wk : (m == 2) ? wv : wo;
        K = 1024; N = 1024; doff = (size_t)m * 1024 * 1024;
    } else if (t < 8192) {
        t -= 4096; src = win;  K = 1024; N = 4096; doff = (size_t)4 * 1024 * 1024;
    } else {
        t -= 8192; src = wout; K = 4096; N = 1024; doff = (size_t)8 * 1024 * 1024;
    }
    int ktiles = K >> 5;
    int k0 = (t % ktiles) << 5;
    int n0 = (t / ktiles) << 5;
    int tx = threadIdx.x, ty = threadIdx.y;   // (32, 8)
    #pragma unroll
    for (int j = 0; j < 4; j++)
        tile[ty + j * 8][tx] = src[(size_t)(k0 + ty + j * 8) * N + n0 + tx];
    __syncthreads();
    #pragma unroll
    for (int j = 0; j < 4; j++)
        dst[doff + (size_t)(n0 + ty + j * 8) * K + k0 + tx] = __float2half_rn(tile[tx][ty + j * 8]);
}

// ---------------- rmsnorm: fp32 + fp16 outputs ----------------
__global__ void rmsnorm_kernel(const float* __restrict__ x, const float* __restrict__ g,
                               float* __restrict__ out, __half* __restrict__ outh, int rnd)
{
    int row = blockIdx.x;
    int tid = threadIdx.x;
    const float4* xr = (const float4*)(x + (size_t)row * DD);
    float4 v = xr[tid];
    float s = v.x*v.x + v.y*v.y + v.z*v.z + v.w*v.w;
    #pragma unroll
    for (int o = 16; o; o >>= 1) s += __shfl_xor_sync(0xffffffffu, s, o);
    __shared__ float red[8];
    if ((tid & 31) == 0) red[tid >> 5] = s;
    __syncthreads();
    float tot = red[0]+red[1]+red[2]+red[3]+red[4]+red[5]+red[6]+red[7];
    float inv = rsqrtf(tot * (1.0f / (float)DD) + 1e-6f);
    const float4* gr = (const float4*)g;
    float4 gv = gr[tid];
    float4 o4;
    o4.x = gv.x * (v.x * inv);
    o4.y = gv.y * (v.y * inv);
    o4.z = gv.z * (v.z * inv);
    o4.w = gv.w * (v.w * inv);
    if (rnd) o4 = cvt4(o4);
    ((float4*)(out + (size_t)row * DD))[tid] = o4;
    __half2* oh = (__half2*)(outh + (size_t)row * DD);
    oh[tid * 2]     = __floats2half2_rn(o4.x, o4.y);
    oh[tid * 2 + 1] = __floats2half2_rn(o4.z, o4.w);
}

// ---------------- EMA chunked scan (G=64 chunks of 32 steps) ----------------
#define EG 64
#define ECH 32

__global__ void ema1_kernel(const float* __restrict__ xn,
                            const float* __restrict__ ap, const float* __restrict__ dp,
                            const float* __restrict__ beta,
                            float* __restrict__ hend)
{
    int idx = blockIdx.x * blockDim.x + threadIdx.x;
    int d = idx & 1023;
    int g = (idx >> 10) & (EG - 1);
    int b = idx >> 16;
    float dec[16], ab[16], h[16];
    #pragma unroll
    for (int n = 0; n < 16; n++) {
        int dn = d * 16 + n;
        float a   = 1.0f / (1.0f + expf(-ap[dn]));
        float ddv = 1.0f / (1.0f + expf(-dp[dn]));
        dec[n] = 1.0f - a * ddv;
        ab[n]  = a * beta[dn];
        h[n]   = 0.0f;
    }
    const float* xp = xn + ((size_t)b * TT + g * ECH) * DD + d;
    #pragma unroll 4
    for (int t = 0; t < ECH; t++) {
        float u = xp[(size_t)t * DD];
        #pragma unroll
        for (int n = 0; n < 16; n++)
            h[n] = fmaf(dec[n], h[n], ab[n] * u);
    }
    size_t base = ((size_t)b * EG + g) * 16 * DD + d;
    #pragma unroll
    for (int n = 0; n < 16; n++)
        hend[base + (size_t)n * DD] = h[n];
}

__global__ void ema2_kernel(const float* __restrict__ hend,
                            const float* __restrict__ ap, const float* __restrict__ dp,
                            float* __restrict__ hstart)
{
    int idx = blockIdx.x * blockDim.x + threadIdx.x;
    int d = idx & 1023;
    int n = (idx >> 10) & 15;
    int b = idx >> 14;
    int dn = d * 16 + n;
    float a   = 1.0f / (1.0f + expf(-ap[dn]));
    float ddv = 1.0f / (1.0f + expf(-dp[dn]));
    float dec = 1.0f - a * ddv;
    float dch = dec;
    #pragma unroll
    for (int j = 0; j < 5; j++) dch *= dch;            // dec^32
    size_t base = ((size_t)b * EG * 16 + n) * DD + d;
    float H = 0.0f;
    #pragma unroll
    for (int gg = 0; gg < EG; gg += 16) {
        float hv[16];
        #pragma unroll
        for (int j = 0; j < 16; j++)
            hv[j] = hend[base + (size_t)(gg + j) * 16 * DD];
        #pragma unroll
        for (int j = 0; j < 16; j++) {
            hstart[base + (size_t)(gg + j) * 16 * DD] = H;
            H = fmaf(dch, H, hv[j]);
        }
    }
}

__global__ void ema3_kernel(const float* __restrict__ xn,
                            const float* __restrict__ ap, const float* __restrict__ dp,
                            const float* __restrict__ beta, const float* __restrict__ eta,
                            const float* __restrict__ hstart,
                            __half* __restrict__ yh)
{
    int idx = blockIdx.x * blockDim.x + threadIdx.x;
    int d = idx & 1023;
    int g = (idx >> 10) & (EG - 1);
    int b = idx >> 16;
    float dec[16], ab[16], et[16], h[16];
    #pragma unroll
    for (int n = 0; n < 16; n++) {
        int dn = d * 16 + n;
        float a   = 1.0f / (1.0f + expf(-ap[dn]));
        float ddv = 1.0f / (1.0f + expf(-dp[dn]));
        dec[n] = 1.0f - a * ddv;
        ab[n]  = a * beta[dn];
        et[n]  = eta[dn];
        h[n]   = hstart[(((size_t)b * EG + g) * 16 + n) * DD + d];
    }
    const float* xp = xn + ((size_t)b * TT + g * ECH) * DD + d;
    __half*      yp = yh + ((size_t)b * TT + g * ECH) * DD + d;
    #pragma unroll 4
    for (int t = 0; t < ECH; t++) {
        float u = xp[(size_t)t * DD];
        float s0 = 0.f, s1 = 0.f, s2 = 0.f, s3 = 0.f;
        #pragma unroll
        for (int n = 0; n < 16; n += 4) {
            h[n]   = fmaf(dec[n],   h[n],   ab[n]   * u);
            h[n+1] = fmaf(dec[n+1], h[n+1], ab[n+1] * u);
            h[n+2] = fmaf(dec[n+2], h[n+2], ab[n+2] * u);
            h[n+3] = fmaf(dec[n+3], h[n+3], ab[n+3] * u);
            s0 = fmaf(et[n],   h[n],   s0);
            s1 = fmaf(et[n+1], h[n+1], s1);
            s2 = fmaf(et[n+2], h[n+2], s2);
            s3 = fmaf(et[n+3], h[n+3], s3);
        }
        yp[(size_t)t * DD] = __float2half_rn((s0 + s1) + (s2 + s3));
    }
}

// ---------------- fp16 GEMM core: 128x128xK64, cp.async 3-stage, all-ldmatrix ---
__device__ __forceinline__ float gelu_tanh(float x)
{
    float z = 0.7978845608028654f * (x + 0.044715f * x * x * x);
    float e = __expf(2.0f * z);
    float t = 1.0f - 2.0f / (e + 1.0f);
    return 0.5f * x * (1.0f + t);
}

#define HSTAGES 3
#define HSTRIDE (128*72)                  // halfs per operand tile (72-stride rows)
#define SMEM_GEMMH (HSTAGES*2*HSTRIDE*2)  // bytes = 110592

// EPI: 0 none, 1 +resid, 2 gelu(acc+bias), 3 acc+bias+resid
// RND: tf32-round fp32 output ; ROPE: fused rotation ; OUTH: fp16 output
template<int EPI, bool RND, bool ROPE, bool OUTH>
__device__ __forceinline__ void gemm_core(const __half* __restrict__ A,
                                          const __half* __restrict__ Bt,
                                          void* __restrict__ Cv,
                                          const float* __restrict__ bias,
                                          const float* __restrict__ resid,
                                          const float2* __restrict__ cs,
                                          int N, int K, int bx, int by, __half* sm)
{
    __half* As = sm;
    __half* Bs = sm + HSTAGES * HSTRIDE;

    const int tid  = threadIdx.x;
    const int lane = tid & 31;
    const int warp = tid >> 5;
    const int wm = (warp & 1) * 64;
    const int wn = (warp >> 1) * 32;
    const int lr = lane >> 2;
    const int lc = lane & 3;
    const int lrow  = lane & 15;
    const int lkoff = (lane >> 4) * 8;    // halfs

    const int r0 = tid >> 1;              // 0..127
    const int hh = (tid & 1) * 32;        // half offset within row
    const __half* Abase = A  + (size_t)(by * 128 + r0) * K + hh;
    const __half* Bbase = Bt + (size_t)(bx * 128 + r0) * K + hh;

    const int kt = K >> 6;

    #pragma unroll
    for (int s = 0; s < HSTAGES - 1; s++) {
        #pragma unroll
        for (int j = 0; j < 4; j++) {
            cpasync16(As + s * HSTRIDE + r0 * 72 + hh + j * 8, Abase + s * 64 + j * 8);
            cpasync16(Bs + s * HSTRIDE + r0 * 72 + hh + j * 8, Bbase + s * 64 + j * 8);
        }
        CP_COMMIT();
    }

    float acc[4][4][4];
    #pragma unroll
    for (int mt = 0; mt < 4; mt++)
        #pragma unroll
        for (int nt = 0; nt < 4; nt++)
            #pragma unroll
            for (int r = 0; r < 4; r++) acc[mt][nt][r] = 0.0f;

    int cb = 0, pb = HSTAGES - 1;
    for (int it = 0; it < kt; it++) {
        CP_WAIT(HSTAGES - 2);
        __syncthreads();

        int nx = it + HSTAGES - 1;
        if (nx < kt) {
            #pragma unroll
            for (int j = 0; j < 4; j++) {
                cpasync16(As + pb * HSTRIDE + r0 * 72 + hh + j * 8, Abase + nx * 64 + j * 8);
                cpasync16(Bs + pb * HSTRIDE + r0 * 72 + hh + j * 8, Bbase + nx * 64 + j * 8);
            }
        }
        CP_COMMIT();
        if (++pb == HSTAGES) pb = 0;

        const __half* Asc = As + cb * HSTRIDE;
        const __half* Bsc = Bs + cb * HSTRIDE;
        if (++cb == HSTAGES) cb = 0;

        #pragma unroll
        for (int ks = 0; ks < 4; ks++) {
            unsigned af[4][4];
            #pragma unroll
            for (int mt = 0; mt < 4; mt++) {
                unsigned addr = (unsigned)__cvta_generic_to_shared(
                    Asc + (wm + mt * 16 + lrow) * 72 + ks * 16 + lkoff);
                ldmx4(af[mt][0], af[mt][1], af[mt][2], af[mt][3], addr);
            }
            unsigned bf[4][2];
            #pragma unroll
            for (int nt2 = 0; nt2 < 2; nt2++) {
                unsigned q0, q1, q2, q3;
                unsigned addr = (unsigned)__cvta_generic_to_shared(
                    Bsc + (wn + nt2 * 16 + lrow) * 72 + ks * 16 + lkoff);
                ldmx4(q0, q1, q2, q3, addr);
                bf[nt2 * 2 + 0][0] = q0; bf[nt2 * 2 + 0][1] = q2;
                bf[nt2 * 2 + 1][0] = q1; bf[nt2 * 2 + 1][1] = q3;
            }
            #pragma unroll
            for (int mt = 0; mt < 4; mt++)
                #pragma unroll
                for (int nt = 0; nt < 4; nt++)
                    mma_f16(acc[mt][nt], af[mt], bf[nt][0], bf[nt][1]);
        }
    }

    if (ROPE && (wn & 32) == 0) {
        #pragma unroll
        for (int mt = 0; mt < 4; mt++) {
            #pragma unroll
            for (int half = 0; half < 2; half++) {
                int rr = by * 128 + wm + mt * 16 + lr + half * 8;
                int t = rr & (TT - 1);
                #pragma unroll
                for (int nt2 = 0; nt2 < 2; nt2++) {
                    #pragma unroll
                    for (int j = 0; j < 2; j++) {
                        int i = nt2 * 8 + 2 * lc + j;
                        float2 cv = cs[t * 16 + i];
                        float x1 = acc[mt][nt2][half * 2 + j];
                        float x2 = acc[mt][nt2 + 2][half * 2 + j];
                        acc[mt][nt2][half * 2 + j]     = x1 * cv.x - x2 * cv.y;
                        acc[mt][nt2 + 2][half * 2 + j] = x2 * cv.x + x1 * cv.y;
                    }
                }
            }
        }
    }

    #pragma unroll
    for (int mt = 0; mt < 4; mt++) {
        #pragma unroll
        for (int nt = 0; nt < 4; nt++) {
            int row = by * 128 + wm + mt * 16 + lr;
            int col = bx * 128 + wn + nt * 8 + 2 * lc;
            #pragma unroll
            for (int half = 0; half < 2; half++) {
                int r = row + half * 8;
                size_t off = (size_t)r * N + col;
                float v0 = acc[mt][nt][half * 2 + 0];
                float v1 = acc[mt][nt][half * 2 + 1];
                if (EPI == 2 || EPI == 3) { v0 += bias[col]; v1 += bias[col + 1]; }
                if (EPI == 2) { v0 = gelu_tanh(v0); v1 = gelu_tanh(v1); }
                if (EPI == 1 || EPI == 3) { v0 += resid[off]; v1 += resid[off + 1]; }
                if (OUTH) {
                    *(__half2*)((__half*)Cv + off) = __floats2half2_rn(v0, v1);
                } else {
                    if (RND) { v0 = f2tf32f(v0); v1 = f2tf32f(v1); }
                    *(float2*)((float*)Cv + off) = make_float2(v0, v1);
                }
            }
        }
    }
}

template<int EPI, bool RND, bool OUTH>
__global__ __launch_bounds__(256, 2)
void tgemm_kernel(const __half* __restrict__ A, const __half* __restrict__ Bt,
                  void* __restrict__ C, const float* __restrict__ bias,
                  const float* __restrict__ resid, int N, int K)
{
    extern __shared__ __half smh[];
    gemm_core<EPI, RND, false, OUTH>(A, Bt, C, bias, resid, nullptr, N, K,
                                     blockIdx.x, blockIdx.y, smh);
}

__global__ __launch_bounds__(256, 2)
void qkv_kernel(const __half* __restrict__ yh, const __half* __restrict__ xnh,
                const __half* __restrict__ wh, const float2* __restrict__ cs,
                float* __restrict__ q, float* __restrict__ k, float* __restrict__ v)
{
    extern __shared__ __half smh[];
    int z = blockIdx.z;
    const __half* A = (z == 2) ? xnh : yh;
    const __half* B = wh + (size_t)z * 1024 * 1024;
    float*        C = (z == 0) ? q : (z == 1) ? k : v;
    gemm_core<0, true, true, false>(A, B, C, nullptr, nullptr, cs, 1024, 1024,
                                    blockIdx.x, blockIdx.y, smh);
}

// ---------------- tf32 mma flash attention, BM=128, BN=64, paired q-tiles ------
#define AT_QS 0
#define AT_KS (128*68)
#define AT_VS (AT_KS + 64*68)
#define AT_PS (AT_VS + 64*72)
#define ATTN_SMEM_FLOATS (AT_PS + 128*68)
#define ATTN_SMEM_BYTES (ATTN_SMEM_FLOATS*4)
#define NQT (TT/128)   // 16

__global__ __launch_bounds__(256, 2)
void attn_kernel(const float* __restrict__ Q, const float* __restrict__ Kk,
                 const float* __restrict__ V, __half* __restrict__ O)
{
    extern __shared__ float sm[];

    const int bh = blockIdx.y;
    const int b = bh >> 4, h = bh & 15;
    const size_t ld = DD;
    const float* Qb = Q  + (size_t)b * TT * ld + h * 64;
    const float* Kb = Kk + (size_t)b * TT * ld + h * 64;
    const float* Vb = V  + (size_t)b * TT * ld + h * 64;
    __half*      Ob = O  + (size_t)b * TT * ld + h * 64;

    const int tid  = threadIdx.x;
    const int lane = tid & 31;
    const int warp = tid >> 5;
    const int lr = lane >> 2;
    const int lc = lane & 3;
    const int lrow  = lane & 15;
    const int lkoff = (lane >> 4) * 4;

    const int ldr0 = tid >> 4;
    const int ldc4 = (tid & 15) << 2;

    #pragma unroll 1
    for (int pass = 0; pass < 2; pass++) {
        const int qt = pass ? (NQT - 1 - blockIdx.x) : blockIdx.x;
        const int nkt = 2 * qt + 2;
        const int row_min = qt * 128 + warp * 16;

        __syncthreads();

        #pragma unroll
        for (int j = 0; j < 4; j++) {
            int r = ldr0 + j * 16;
            cpasync16(&sm[AT_KS + r * 68 + ldc4], Kb + (size_t)r * ld + ldc4);
        }
        CP_COMMIT();
        #pragma unroll
        for (int j = 0; j < 4; j++) {
            int r = ldr0 + j * 16;
            cpasync16(&sm[AT_VS + r * 72 + ldc4], Vb + (size_t)r * ld + ldc4);
        }
        CP_COMMIT();

        for (int i = tid; i < 128 * 16; i += 256) {
            int r = i >> 4, c4 = (i & 15) << 2;
            float4 qv = *(const float4*)(Qb + (size_t)(qt * 128 + r) * ld + c4);
            qv.x *= 0.125f; qv.y *= 0.125f; qv.z *= 0.125f; qv.w *= 0.125f;
            *(float4*)&sm[AT_QS + r * 68 + c4] = qv;
        }

        float m_i[2] = {-1e30f, -1e30f};
        float l_i[2] = {0.0f, 0.0f};
        float o[8][4];
        #pragma unroll
        for (int nt = 0; nt < 8; nt++)
            #pragma unroll
            for (int r = 0; r < 4; r++) o[nt][r] = 0.0f;

        for (int kt = 0; kt < nkt; kt++) {
            const bool active = (kt * 64 <= row_min + 15);
            float s[8][4];

            CP_WAIT(1);
            __syncthreads();

            if (active) {
                #pragma unroll
                for (int nt = 0; nt < 8; nt++)
                    #pragma unroll
                    for (int r = 0; r < 4; r++) s[nt][r] = 0.0f;

                #pragma unroll
                for (int kb = 0; kb < 8; kb++) {
                    unsigned af[4];
                    unsigned qaddr = (unsigned)__cvta_generic_to_shared(
                        &sm[AT_QS + (warp * 16 + lrow) * 68 + kb * 8 + lkoff]);
                    ldmx4(af[0], af[1], af[2], af[3], qaddr);
                    unsigned bf[8][2];
                    #pragma unroll
                    for (int nt2 = 0; nt2 < 4; nt2++) {
                        unsigned q0, q1, q2, q3;
                        unsigned kaddr = (unsigned)__cvta_generic_to_shared(
                            &sm[AT_KS + (nt2 * 16 + lrow) * 68 + kb * 8 + lkoff]);
                        ldmx4(q0, q1, q2, q3, kaddr);
                        bf[nt2 * 2 + 0][0] = q0; bf[nt2 * 2 + 0][1] = q2;
                        bf[nt2 * 2 + 1][0] = q1; bf[nt2 * 2 + 1][1] = q3;
                    }
                    #pragma unroll
                    for (int nt = 0; nt < 8; nt++)
                        mma_tf32(s[nt], af, bf[nt][0], bf[nt][1]);
                }
            }

            __syncthreads();
            if (kt + 1 < nkt) {
                #pragma unroll
                for (int j = 0; j < 4; j++) {
                    int r = ldr0 + j * 16;
                    cpasync16(&sm[AT_KS + r * 68 + ldc4],
                              Kb + (size_t)((kt + 1) * 64 + r) * ld + ldc4);
                }
            }
            CP_COMMIT();

            if (active) {
                if (kt * 64 + 63 > row_min) {
                    #pragma unroll
                    for (int nt = 0; nt < 8; nt++)
                        #pragma unroll
                        for (int r = 0; r < 4; r++) {
                            int col = kt * 64 + nt * 8 + 2 * lc + (r & 1);
                            int row = row_min + lr + 8 * (r >> 1);
                            if (col > row) s[nt][r] = -1e30f;
                        }
                }

                #pragma unroll
                for (int h2 = 0; h2 < 2; h2++) {
                    float rm = -1e30f;
                    #pragma unroll
                    for (int nt = 0; nt < 8; nt++)
                        rm = fmaxf(rm, fmaxf(s[nt][2*h2], s[nt][2*h2+1]));
                    rm = fmaxf(rm, __shfl_xor_sync(0xffffffffu, rm, 1));
                    rm = fmaxf(rm, __shfl_xor_sync(0xffffffffu, rm, 2));
                    float mn = fmaxf(m_i[h2], rm);
                    float alpha = __expf(m_i[h2] - mn);
                    m_i[h2] = mn;
                    float rs = 0.0f;
                    #pragma unroll
                    for (int nt = 0; nt < 8; nt++) {
                        float p0 = __expf(s[nt][2*h2]   - mn);
                        float p1 = __expf(s[nt][2*h2+1] - mn);
                        s[nt][2*h2]   = p0;
                        s[nt][2*h2+1] = p1;
                        rs += p0 + p1;
                    }
                    rs += __shfl_xor_sync(0xffffffffu, rs, 1);
                    rs += __shfl_xor_sync(0xffffffffu, rs, 2);
                    l_i[h2] = l_i[h2] * alpha + rs;
                    #pragma unroll
                    for (int nt = 0; nt < 8; nt++) {
                        o[nt][2*h2]   *= alpha;
                        o[nt][2*h2+1] *= alpha;
                    }
                }

                #pragma unroll
                for (int nt = 0; nt < 8; nt++)
                    #pragma unroll
                    for (int r = 0; r < 4; r++) {
                        int row = warp * 16 + lr + 8 * (r >> 1);
                        int col = nt * 8 + 2 * lc + (r & 1);
                        sm[AT_PS + row * 68 + col] = f2tf32f(s[nt][r]);
                    }
            }

            CP_WAIT(1);
            __syncthreads();

            if (active) {
                #pragma unroll
                for (int kb = 0; kb < 8; kb++) {
                    unsigned af[4];
                    unsigned paddr = (unsigned)__cvta_generic_to_shared(
                        &sm[AT_PS + (warp * 16 + lrow) * 68 + kb * 8 + lkoff]);
                    ldmx4(af[0], af[1], af[2], af[3], paddr);
                    #pragma unroll
                    for (int nt = 0; nt < 8; nt++) {
                        unsigned b0 = __float_as_uint(sm[AT_VS + (kb * 8 + lc)     * 72 + nt * 8 + lr]);
                        unsigned b1 = __float_as_uint(sm[AT_VS + (kb * 8 + lc + 4) * 72 + nt * 8 + lr]);
                        mma_tf32(o[nt], af, b0, b1);
                    }
                }
            }

            __syncthreads();
            if (kt + 1 < nkt) {
                #pragma unroll
                for (int j = 0; j < 4; j++) {
                    int r = ldr0 + j * 16;
                    cpasync16(&sm[AT_VS + r * 72 + ldc4],
                              Vb + (size_t)((kt + 1) * 64 + r) * ld + ldc4);
                }
            }
            CP_COMMIT();
        }

        #pragma unroll
        for (int h2 = 0; h2 < 2; h2++) {
            float inv = 1.0f / l_i[h2];
            int row = qt * 128 + warp * 16 + lr + 8 * h2;
            #pragma unroll
            for (int nt = 0; nt < 8; nt++) {
                int col = nt * 8 + 2 * lc;
                *(__half2*)(Ob + (size_t)row * ld + col) =
                    __floats2half2_rn(o[nt][2*h2] * inv, o[nt][2*h2+1] * inv);
            }
        }
    }
}

// ---------------- launch ----------------
extern "C" void kernel_launch(void* const* d_in, const int* in_sizes, int n_in,
                              void* d_out, int out_size)
{
    const float* x       = (const float*)d_in[0];
    const float* w_q     = (const float*)d_in[1];
    const float* w_k     = (const float*)d_in[2];
    const float* w_v     = (const float*)d_in[3];
    const float* w_o     = (const float*)d_in[4];
    const float* alpha_p = (const float*)d_in[5];
    const float* delta_p = (const float*)d_in[6];
    const float* beta    = (const float*)d_in[7];
    const float* eta     = (const float*)d_in[8];
    const float* g1      = (const float*)d_in[9];
    const float* g2      = (const float*)d_in[10];
    const float* w_in    = (const float*)d_in[11];
    const float* b_in    = (const float*)d_in[12];
    const float* w_out   = (const float*)d_in[13];
    const float* b_out   = (const float*)d_in[14];
    float* out = (float*)d_out;

    float *xn, *q, *k, *v, *x1, *xn2, *e1, *e2;
    __half *xnh, *yh, *aoh, *xn2h, *hbh, *wh;
    float2* cs;
    cudaGetSymbolAddress((void**)&xn,   g_xn);
    cudaGetSymbolAddress((void**)&xnh,  g_xnh);
    cudaGetSymbolAddress((void**)&yh,   g_yh);
    cudaGetSymbolAddress((void**)&q,    g_q);
    cudaGetSymbolAddress((void**)&k,    g_k);
    cudaGetSymbolAddress((void**)&v,    g_v);
    cudaGetSymbolAddress((void**)&aoh,  g_aoh);
    cudaGetSymbolAddress((void**)&x1,   g_x1);
    cudaGetSymbolAddress((void**)&xn2,  g_xn2);
    cudaGetSymbolAddress((void**)&xn2h, g_xn2h);
    cudaGetSymbolAddress((void**)&hbh,  g_hbh);
    cudaGetSymbolAddress((void**)&wh,   g_wh);
    cudaGetSymbolAddress((void**)&e1,   g_e1);
    cudaGetSymbolAddress((void**)&e2,   g_e2);
    cudaGetSymbolAddress((void**)&cs,   g_cs);

    cudaFuncSetAttribute(attn_kernel, cudaFuncAttributeMaxDynamicSharedMemorySize,
                         ATTN_SMEM_BYTES);
    cudaFuncSetAttribute(qkv_kernel, cudaFuncAttributeMaxDynamicSharedMemorySize, SMEM_GEMMH);
    cudaFuncSetAttribute((const void*)tgemm_kernel<1,false,false>, cudaFuncAttributeMaxDynamicSharedMemorySize, SMEM_GEMMH);
    cudaFuncSetAttribute((const void*)tgemm_kernel<2,false,true>,  cudaFuncAttributeMaxDynamicSharedMemorySize, SMEM_GEMMH);
    cudaFuncSetAttribute((const void*)tgemm_kernel<3,false,false>, cudaFuncAttributeMaxDynamicSharedMemorySize, SMEM_GEMMH);

    wtrans_kernel<<<12288 + 128, dim3(32, 8)>>>(w_q, w_k, w_v, w_o, w_in, w_out, wh, cs);

    rmsnorm_kernel<<<BT, 256>>>(x, g1, xn, xnh, 1);

    ema1_kernel<<<(BB * EG * DD) / 256, 256>>>(xn, alpha_p, delta_p, beta, e1);
    ema2_kernel<<<(BB * 16 * DD) / 256, 256>>>(e1, alpha_p, delta_p, e2);
    ema3_kernel<<<(BB * EG * DD) / 256, 256>>>(xn, alpha_p, delta_p, beta, eta, e2, yh);

    qkv_kernel<<<dim3(8, BT / 128, 3), 256, SMEM_GEMMH>>>(yh, xnh, wh, cs, q, k, v);

    attn_kernel<<<dim3(NQT / 2, BB * HH), 256, ATTN_SMEM_BYTES>>>(q, k, v, aoh);

    tgemm_kernel<1,false,false><<<dim3(8, BT / 128), 256, SMEM_GEMMH>>>(
        aoh, wh + 3 * 1024 * 1024, x1, nullptr, x, 1024, 1024);

    rmsnorm_kernel<<<BT, 256>>>(x1, g2, xn2, xn2h, 1);

    tgemm_kernel<2,false,true><<<dim3(32, BT / 128), 256, SMEM_GEMMH>>>(
        xn2h, wh + 4 * 1024 * 1024, hbh, b_in, nullptr, 4096, 1024);
    tgemm_kernel<3,false,false><<<dim3(8, BT / 128), 256, SMEM_GEMMH>>>(
        hbh, wh + 8 * 1024 * 1024, out, b_out, x1, 1024, 4096);
}